// round 9
// baseline (speedup 1.0000x reference)
#include <cuda_runtime.h>
#include <cuda_bf16.h>
#include <cstdint>

// RVQ: x [16,2048,128] f32, codebooks [8,1024,128] f32
// out (float32): indices [B*N*Q] ++ quantized [B*N*D] ++ commits [Q]
// Core: bf16 2-term-split GEMM (HH+HM+MH, HMMA) + exact fp32 8-candidate rescue.

#define TOKENS   32768
#define DDIM     128
#define KCODES   1024
#define QSTAGES  8
#define BM       128
#define NTILE    128
#define NTILES   (KCODES / NTILE)   // 8
#define NTHREADS 512
#define NBLOCKS  (TOKENS / BM)      // 256

#define TERM_BYTES  32768    // 128 rows x 256 B
#define A_OFF       0        // 2 terms: 65536 B
#define B_OFF       65536    // 2 buffers x 65536 B
#define B_BUF_BYTES 65536
#define CHOSEN_OFF  196608
#define REDV_OFF    197120   // [4][128] f32
#define REDI_OFF    199168
#define REDV2_OFF   201216
#define REDI2_OFF   203264
#define SMEM_TOTAL  205312

__device__ float g_res[TOKENS * DDIM];
__device__ float g_c2[QSTAGES * KCODES];
__device__ float g_partial[QSTAGES * NBLOCKS];
__device__ unsigned char g_cbs[(size_t)QSTAGES * NTILES * 2 * TERM_BYTES]; // 4MB

// ---------------------------------------------------------------------------
__device__ __forceinline__ void cp16(uint32_t dst, const void* src) {
    asm volatile("cp.async.cg.shared.global [%0], [%1], 16;" :: "r"(dst), "l"(src));
}
__device__ __forceinline__ void cp_commit() { asm volatile("cp.async.commit_group;"); }
template<int N> __device__ __forceinline__ void cp_wait() {
    asm volatile("cp.async.wait_group %0;" :: "n"(N) : "memory");
}
__device__ __forceinline__ uint32_t smem_u32(const void* p) {
    uint32_t a;
    asm("{ .reg .u64 t; cvta.to.shared.u64 t, %1; cvt.u32.u64 %0, t; }" : "=r"(a) : "l"(p));
    return a;
}
__device__ __forceinline__ void ldsm4(uint32_t& r0, uint32_t& r1, uint32_t& r2,
                                      uint32_t& r3, uint32_t addr) {
    asm volatile("ldmatrix.sync.aligned.m8n8.x4.shared.b16 {%0,%1,%2,%3}, [%4];"
                 : "=r"(r0), "=r"(r1), "=r"(r2), "=r"(r3) : "r"(addr));
}
__device__ __forceinline__ void mma16816(float& d0, float& d1, float& d2, float& d3,
                                         uint32_t a0, uint32_t a1, uint32_t a2,
                                         uint32_t a3, uint32_t b0, uint32_t b1) {
    asm volatile(
        "mma.sync.aligned.m16n8k16.row.col.f32.bf16.bf16.f32 "
        "{%0,%1,%2,%3}, {%4,%5,%6,%7}, {%8,%9}, {%0,%1,%2,%3};"
        : "+f"(d0), "+f"(d1), "+f"(d2), "+f"(d3)
        : "r"(a0), "r"(a1), "r"(a2), "r"(a3), "r"(b0), "r"(b1));
}
__device__ __forceinline__ bool dless(float a, int ia, float b, int ib) {
    return a < b || (a == b && ia < ib);
}
__device__ __forceinline__ void merge2(float& v1, int& j1, float& v2, int& j2,
                                       float o1, int oj1, float o2, int oj2) {
    float nv1, nv2; int nj1, nj2;
    if (dless(o1, oj1, v1, j1)) {
        nv1 = o1; nj1 = oj1;
        if (dless(v1, j1, o2, oj2)) { nv2 = v1; nj2 = j1; }
        else                        { nv2 = o2; nj2 = oj2; }
    } else {
        nv1 = v1; nj1 = j1;
        if (dless(o1, oj1, v2, j2)) { nv2 = o1; nj2 = oj1; }
        else                        { nv2 = v2; nj2 = j2; }
    }
    v1 = nv1; j1 = nj1; v2 = nv2; j2 = nj2;
}

// smem element (row, bf16-col c) -> byte:  r*256 + ((c>>3) ^ (r&7))*16 + (c&7)*2
__device__ __forceinline__ void split2(float4 v, uint2& H, uint2& M) {
    float a[4] = {v.x, v.y, v.z, v.w};
    unsigned short hs[4], ms[4];
    #pragma unroll
    for (int i = 0; i < 4; i++) {
        __nv_bfloat16 hb = __float2bfloat16_rn(a[i]);
        float r1 = a[i] - __bfloat162float(hb);
        __nv_bfloat16 mb = __float2bfloat16_rn(r1);
        hs[i] = __bfloat16_as_ushort(hb);
        ms[i] = __bfloat16_as_ushort(mb);
    }
    H.x = hs[0] | ((uint32_t)hs[1] << 16); H.y = hs[2] | ((uint32_t)hs[3] << 16);
    M.x = ms[0] | ((uint32_t)ms[1] << 16); M.y = ms[2] | ((uint32_t)ms[3] << 16);
}

// ---------------------------------------------------------------------------
__global__ void prep_kernel(const float* __restrict__ cb) {
    int gr = blockIdx.x * blockDim.x + threadIdx.x;   // 0..8191
    if (gr >= QSTAGES * KCODES) return;
    int stage = gr >> 10, row = gr & 1023;
    int tile = row >> 7, r = row & 127;
    const float4* src = (const float4*)(cb + (size_t)gr * DDIM);
    unsigned char* base0 = g_cbs + (size_t)((stage * NTILES + tile) * 2) * TERM_BYTES;
    #pragma unroll 4
    for (int c4 = 0; c4 < 32; c4++) {
        uint2 H, M;
        split2(src[c4], H, M);
        uint32_t so = (uint32_t)r * 256 + (uint32_t)(((c4 >> 1) ^ (r & 7)) * 16)
                    + (uint32_t)((c4 & 1) * 8);
        *(uint2*)(base0 + so)              = H;
        *(uint2*)(base0 + TERM_BYTES + so) = M;
    }
}

// ---------------------------------------------------------------------------
__global__ void c2_kernel(const float* __restrict__ cb) {
    int warp = (blockIdx.x * blockDim.x + threadIdx.x) >> 5;
    int lane = threadIdx.x & 31;
    const float4* row = (const float4*)(cb + (size_t)warp * DDIM);
    float4 v = row[lane];
    float s = v.x * v.x + v.y * v.y + v.z * v.z + v.w * v.w;
    #pragma unroll
    for (int o = 16; o > 0; o >>= 1) s += __shfl_down_sync(0xffffffffu, s, o);
    if (lane == 0) g_c2[warp] = s;
}

// ---------------------------------------------------------------------------
extern __shared__ char sm[];

__global__ __launch_bounds__(NTHREADS, 1)
void stage_kernel(const float* __restrict__ x,
                  const float* __restrict__ cb_all,
                  float* __restrict__ out,
                  int stage, int is_last) {
    const uint32_t smb = smem_u32(sm);
    const int tid = threadIdx.x, wid = tid >> 5, lid = tid & 31;
    const int tok0 = blockIdx.x * BM;
    const int warpM = wid & 3, warpN = wid >> 2;   // 4 x 4 warp grid
    const float*  src = (stage == 0) ? x : (const float*)g_res;
    const float*  cbf = cb_all + (size_t)stage * KCODES * DDIM;
    const float4* cb4 = (const float4*)cbf;
    const float*  c2  = g_c2 + stage * KCODES;

    int*   chosen = (int*)(sm + CHOSEN_OFF);
    float* redv   = (float*)(sm + REDV_OFF);
    int*   redi   = (int*)(sm + REDI_OFF);
    float* redv2  = (float*)(sm + REDV2_OFF);
    int*   redi2  = (int*)(sm + REDI2_OFF);

    // ---- preload B tiles 0,1 ----
    const unsigned char* gcb = g_cbs + (size_t)(stage * NTILES * 2) * TERM_BYTES;
    {
        uint32_t b0 = smb + B_OFF, b1 = smb + B_OFF + B_BUF_BYTES;
        #pragma unroll
        for (int k = 0; k < 8; k++) {
            int u = tid + k * NTHREADS;   // 0..4095 16B units
            cp16(b0 + (uint32_t)u * 16, gcb + (size_t)u * 16);
        }
        cp_commit();
        #pragma unroll
        for (int k = 0; k < 8; k++) {
            int u = tid + k * NTHREADS;
            cp16(b1 + (uint32_t)u * 16, gcb + B_BUF_BYTES + (size_t)u * 16);
        }
        cp_commit();
    }

    // ---- A split: residual -> 2 bf16 terms in swizzled smem ----
    {
        const float4* s4 = (const float4*)src + (size_t)tok0 * 32;
        #pragma unroll
        for (int k = 0; k < 8; k++) {
            int f = tid + k * NTHREADS;
            int r = f >> 5, c4 = f & 31;
            uint2 H, M;
            split2(s4[f], H, M);
            uint32_t so = (uint32_t)r * 256 + (uint32_t)(((c4 >> 1) ^ (r & 7)) * 16)
                        + (uint32_t)((c4 & 1) * 8);
            *(uint2*)(sm + A_OFF + so)              = H;
            *(uint2*)(sm + A_OFF + TERM_BYTES + so) = M;
        }
    }
    __syncthreads();

    // ldmatrix lane address components
    uint32_t aRowByte[2], aRx[2];
    #pragma unroll
    for (int mi = 0; mi < 2; mi++) {
        int row = warpM * 32 + mi * 16 + (lid & 15);
        aRowByte[mi] = (uint32_t)row * 256;
        aRx[mi] = (uint32_t)(row & 7);
    }
    const uint32_t aKh = (uint32_t)(lid >> 4);
    uint32_t bRowByte[2], bRx[2];
    #pragma unroll
    for (int pi = 0; pi < 2; pi++) {
        int row = warpN * 32 + pi * 16 + ((lid >> 4) << 3) + (lid & 7);
        bRowByte[pi] = (uint32_t)row * 256;
        bRx[pi] = (uint32_t)(row & 7);
    }
    const uint32_t bKh = (uint32_t)((lid >> 3) & 1);

    // products: HH, HM, MH
    const int pa[3] = {0, 0, 1};
    const int pb[3] = {0, 1, 0};

    // per-thread running top-2 per (mi, half)
    float b1v[2][2], b2v[2][2]; int b1i[2][2], b2i[2][2];
    #pragma unroll
    for (int mi = 0; mi < 2; mi++)
        #pragma unroll
        for (int h = 0; h < 2; h++) {
            b1v[mi][h] = 3.4e38f; b2v[mi][h] = 3.4e38f;
            b1i[mi][h] = 0;       b2i[mi][h] = 0;
        }

    for (int t = 0; t < NTILES; t++) {
        if (t < NTILES - 1) cp_wait<1>(); else cp_wait<0>();
        __syncthreads();
        const uint32_t bbuf = smb + B_OFF + (uint32_t)(t & 1) * B_BUF_BYTES;

        float acc[2][4][4];
        #pragma unroll
        for (int mi = 0; mi < 2; mi++)
            #pragma unroll
            for (int ni = 0; ni < 4; ni++)
                #pragma unroll
                for (int q = 0; q < 4; q++) acc[mi][ni][q] = 0.f;

        #pragma unroll
        for (int p = 0; p < 3; p++) {
            const uint32_t abase = smb + A_OFF + (uint32_t)pa[p] * TERM_BYTES;
            const uint32_t bbase = bbuf + (uint32_t)pb[p] * TERM_BYTES;
            #pragma unroll
            for (int k8 = 0; k8 < 8; k8++) {
                const uint32_t ku = (uint32_t)(k8 * 2);
                uint32_t a[2][4];
                #pragma unroll
                for (int mi = 0; mi < 2; mi++) {
                    uint32_t addr = abase + aRowByte[mi] + (((ku + aKh) ^ aRx[mi]) << 4);
                    ldsm4(a[mi][0], a[mi][1], a[mi][2], a[mi][3], addr);
                }
                uint32_t b[2][4];
                #pragma unroll
                for (int pi = 0; pi < 2; pi++) {
                    uint32_t addr = bbase + bRowByte[pi] + (((ku + bKh) ^ bRx[pi]) << 4);
                    ldsm4(b[pi][0], b[pi][1], b[pi][2], b[pi][3], addr);
                }
                #pragma unroll
                for (int mi = 0; mi < 2; mi++)
                    #pragma unroll
                    for (int pi = 0; pi < 2; pi++) {
                        mma16816(acc[mi][pi*2][0], acc[mi][pi*2][1],
                                 acc[mi][pi*2][2], acc[mi][pi*2][3],
                                 a[mi][0], a[mi][1], a[mi][2], a[mi][3],
                                 b[pi][0], b[pi][1]);
                        mma16816(acc[mi][pi*2+1][0], acc[mi][pi*2+1][1],
                                 acc[mi][pi*2+1][2], acc[mi][pi*2+1][3],
                                 a[mi][0], a[mi][1], a[mi][2], a[mi][3],
                                 b[pi][2], b[pi][3]);
                    }
            }
        }

        // top-2 argmin epilogue (ascending code order)
        const int codebase = t * NTILE + warpN * 32;
        #pragma unroll
        for (int ni = 0; ni < 4; ni++) {
            int code0 = codebase + ni * 8 + (lid & 3) * 2;
            float2 cc = __ldg((const float2*)(c2 + code0));
            #pragma unroll
            for (int mi = 0; mi < 2; mi++) {
                #pragma unroll
                for (int h = 0; h < 2; h++) {
                    float d0 = cc.x - 2.f * acc[mi][ni][h * 2];
                    float d1 = cc.y - 2.f * acc[mi][ni][h * 2 + 1];
                    if (d0 < b1v[mi][h]) {
                        b2v[mi][h] = b1v[mi][h]; b2i[mi][h] = b1i[mi][h];
                        b1v[mi][h] = d0; b1i[mi][h] = code0;
                    } else if (d0 < b2v[mi][h]) { b2v[mi][h] = d0; b2i[mi][h] = code0; }
                    if (d1 < b1v[mi][h]) {
                        b2v[mi][h] = b1v[mi][h]; b2i[mi][h] = b1i[mi][h];
                        b1v[mi][h] = d1; b1i[mi][h] = code0 + 1;
                    } else if (d1 < b2v[mi][h]) { b2v[mi][h] = d1; b2i[mi][h] = code0 + 1; }
                }
            }
        }

        __syncthreads();
        if (t + 2 < NTILES) {
            uint32_t bb = smb + B_OFF + (uint32_t)(t & 1) * B_BUF_BYTES;
            const unsigned char* gs = gcb + (size_t)(t + 2) * B_BUF_BYTES;
            #pragma unroll
            for (int k = 0; k < 8; k++) {
                int u = tid + k * NTHREADS;
                cp16(bb + (uint32_t)u * 16, gs + (size_t)u * 16);
            }
            cp_commit();
        }
    }

    // quad reduce with top-2 merge; write per-contributor (warpN) candidates
    #pragma unroll
    for (int mi = 0; mi < 2; mi++)
        #pragma unroll
        for (int h = 0; h < 2; h++) {
            float v1 = b1v[mi][h], v2 = b2v[mi][h];
            int   j1 = b1i[mi][h], j2 = b2i[mi][h];
            #pragma unroll
            for (int off = 1; off <= 2; off <<= 1) {
                float o1 = __shfl_xor_sync(0xffffffffu, v1, off);
                int   oj1 = __shfl_xor_sync(0xffffffffu, j1, off);
                float o2 = __shfl_xor_sync(0xffffffffu, v2, off);
                int   oj2 = __shfl_xor_sync(0xffffffffu, j2, off);
                merge2(v1, j1, v2, j2, o1, oj1, o2, oj2);
            }
            if ((lid & 3) == 0) {
                int row = warpM * 32 + mi * 16 + h * 8 + (lid >> 2);
                redv[warpN * 128 + row]  = v1;
                redi[warpN * 128 + row]  = j1;
                redv2[warpN * 128 + row] = v2;
                redi2[warpN * 128 + row] = j2;
            }
        }
    __syncthreads();

    // exact fp32 rescue: thread (token, contributor) evaluates that
    // contributor's 2 candidates exactly and writes exact distances back.
    {
        int token = tid >> 2, c = tid & 3;         // 128 tokens x 4 contributors
        int j1 = redi[c * 128 + token];
        int j2 = redi2[c * 128 + token];
        const float* rrow = src + (size_t)(tok0 + token) * DDIM;
        const float* c1row = cbf + (size_t)j1 * DDIM;
        const float* c2row = cbf + (size_t)j2 * DDIM;
        float acc1 = 0.f, acc2 = 0.f;
        #pragma unroll 16
        for (int d = 0; d < DDIM; d++) {
            float r = __ldg(&rrow[d]);
            acc1 = fmaf(r, __ldg(&c1row[d]), acc1);
            acc2 = fmaf(r, __ldg(&c2row[d]), acc2);
        }
        redv[c * 128 + token]  = __ldg(&c2[j1]) - 2.f * acc1;
        redv2[c * 128 + token] = __ldg(&c2[j2]) - 2.f * acc2;
    }
    __syncthreads();
    if (tid < BM) {
        float bv = 3.4e38f; int bi = 0x7fffffff;
        #pragma unroll
        for (int c = 0; c < 4; c++) {
            float v1 = redv[c * 128 + tid];  int j1 = redi[c * 128 + tid];
            float v2 = redv2[c * 128 + tid]; int j2 = redi2[c * 128 + tid];
            if (dless(v1, j1, bv, bi)) { bv = v1; bi = j1; }
            if (dless(v2, j2, bv, bi)) { bv = v2; bi = j2; }
        }
        chosen[tid] = bi;
        out[(size_t)(tok0 + tid) * QSTAGES + stage] = (float)bi;
    }
    __syncthreads();

    // residual update + commit partial + optional quantized output (fp32 exact)
    float4*       res4 = (float4*)g_res + (size_t)tok0 * 32;
    const float4* s4   = (const float4*)src + (size_t)tok0 * 32;
    const float4* x4   = (const float4*)x + (size_t)tok0 * 32;
    float4*       q4   = (float4*)(out + (size_t)TOKENS * QSTAGES) + (size_t)tok0 * 32;

    float psum = 0.f;
    #pragma unroll
    for (int k = 0; k < 8; k++) {
        int f = tid + k * NTHREADS;
        int tk = f >> 5, d4 = f & 31;
        float4 rv = s4[f];
        float4 cv = cb4[(size_t)chosen[tk] * 32 + d4];
        float4 nv = make_float4(rv.x - cv.x, rv.y - cv.y, rv.z - cv.z, rv.w - cv.w);
        res4[tk * 32 + d4] = nv;
        psum += nv.x * nv.x + nv.y * nv.y + nv.z * nv.z + nv.w * nv.w;
        if (is_last) {
            float4 xv = x4[f];
            q4[tk * 32 + d4] = make_float4(xv.x - nv.x, xv.y - nv.y,
                                           xv.z - nv.z, xv.w - nv.w);
        }
    }
    #pragma unroll
    for (int o = 16; o > 0; o >>= 1) psum += __shfl_down_sync(0xffffffffu, psum, o);
    __syncthreads();
    if (lid == 0) redv[wid] = psum;
    __syncthreads();
    if (tid == 0) {
        float s = 0.f;
        #pragma unroll
        for (int w2 = 0; w2 < 16; w2++) s += redv[w2];
        g_partial[stage * NBLOCKS + blockIdx.x] = s;
    }
}

// ---------------------------------------------------------------------------
__global__ void finish_kernel(float* __restrict__ out) {
    int q = threadIdx.x;
    if (q < QSTAGES) {
        float s = 0.f;
        for (int b = 0; b < NBLOCKS; b++) s += g_partial[q * NBLOCKS + b];
        out[(size_t)TOKENS * QSTAGES + (size_t)TOKENS * DDIM + q] =
            s / (float)(TOKENS * DDIM);
    }
}

extern "C" void kernel_launch(void* const* d_in, const int* in_sizes, int n_in,
                              void* d_out, int out_size) {
    const float* x  = (const float*)d_in[0];
    const float* cb = (const float*)d_in[1];
    float* out = (float*)d_out;

    cudaFuncSetAttribute(stage_kernel,
                         cudaFuncAttributeMaxDynamicSharedMemorySize, SMEM_TOTAL);

    prep_kernel<<<64, 128>>>(cb);
    c2_kernel<<<1024, 256>>>(cb);
    for (int s = 0; s < QSTAGES; s++) {
        stage_kernel<<<NBLOCKS, NTHREADS, SMEM_TOTAL>>>(x, cb, out, s,
                                                        (s == QSTAGES - 1) ? 1 : 0);
    }
    finish_kernel<<<1, 32>>>(out);
}

// round 10
// speedup vs baseline: 2.3353x; 2.3353x over previous
#include <cuda_runtime.h>
#include <cuda_bf16.h>
#include <cstdint>

// RVQ: x [16,2048,128] f32, codebooks [8,1024,128] f32
// out (float32): indices [B*N*Q] ++ quantized [B*N*D] ++ commits [Q]
// Core: bf16 2-term split (HH+HM+MH), HMMA, A_H registerized, exact top-2 rescue.

#define TOKENS   32768
#define DDIM     128
#define KCODES   1024
#define QSTAGES  8
#define BM       128
#define NTILE    64
#define NTILES   (KCODES / NTILE)   // 16
#define NTHREADS 512
#define NBLOCKS  (TOKENS / BM)      // 256

#define A_TERM_BYTES 32768   // 128 rows x 256 B
#define B_TERM_BYTES 16384   // 64 rows x 256 B
#define A_OFF        0       // 2 planes: 65536 B
#define B_OFF        65536   // 2 buffers x 32768 B
#define B_BUF_BYTES  32768
#define CHOSEN_OFF   131072
#define REDV_OFF     131584  // [2][128]
#define REDI_OFF     132608
#define REDV2_OFF    133632
#define REDI2_OFF    134656
#define SMEM_TOTAL   135680

__device__ float g_res[TOKENS * DDIM];
__device__ float g_c2[QSTAGES * KCODES];
__device__ float g_partial[QSTAGES * NBLOCKS];
__device__ unsigned char g_cbs[(size_t)QSTAGES * NTILES * 2 * B_TERM_BYTES]; // 4MB

// ---------------------------------------------------------------------------
__device__ __forceinline__ void cp16(uint32_t dst, const void* src) {
    asm volatile("cp.async.cg.shared.global [%0], [%1], 16;" :: "r"(dst), "l"(src));
}
__device__ __forceinline__ void cp_commit() { asm volatile("cp.async.commit_group;"); }
template<int N> __device__ __forceinline__ void cp_wait() {
    asm volatile("cp.async.wait_group %0;" :: "n"(N) : "memory");
}
__device__ __forceinline__ uint32_t smem_u32(const void* p) {
    uint32_t a;
    asm("{ .reg .u64 t; cvta.to.shared.u64 t, %1; cvt.u32.u64 %0, t; }" : "=r"(a) : "l"(p));
    return a;
}
__device__ __forceinline__ void ldsm4(uint32_t& r0, uint32_t& r1, uint32_t& r2,
                                      uint32_t& r3, uint32_t addr) {
    asm volatile("ldmatrix.sync.aligned.m8n8.x4.shared.b16 {%0,%1,%2,%3}, [%4];"
                 : "=r"(r0), "=r"(r1), "=r"(r2), "=r"(r3) : "r"(addr));
}
__device__ __forceinline__ void mma16816(float& d0, float& d1, float& d2, float& d3,
                                         uint32_t a0, uint32_t a1, uint32_t a2,
                                         uint32_t a3, uint32_t b0, uint32_t b1) {
    asm volatile(
        "mma.sync.aligned.m16n8k16.row.col.f32.bf16.bf16.f32 "
        "{%0,%1,%2,%3}, {%4,%5,%6,%7}, {%8,%9}, {%0,%1,%2,%3};"
        : "+f"(d0), "+f"(d1), "+f"(d2), "+f"(d3)
        : "r"(a0), "r"(a1), "r"(a2), "r"(a3), "r"(b0), "r"(b1));
}
__device__ __forceinline__ bool dless(float a, int ia, float b, int ib) {
    return a < b || (a == b && ia < ib);
}
__device__ __forceinline__ void merge2(float& v1, int& j1, float& v2, int& j2,
                                       float o1, int oj1, float o2, int oj2) {
    float nv1, nv2; int nj1, nj2;
    if (dless(o1, oj1, v1, j1)) {
        nv1 = o1; nj1 = oj1;
        if (dless(v1, j1, o2, oj2)) { nv2 = v1; nj2 = j1; }
        else                        { nv2 = o2; nj2 = oj2; }
    } else {
        nv1 = v1; nj1 = j1;
        if (dless(o1, oj1, v2, j2)) { nv2 = o1; nj2 = oj1; }
        else                        { nv2 = v2; nj2 = j2; }
    }
    v1 = nv1; j1 = nj1; v2 = nv2; j2 = nj2;
}

// smem element (row, bf16-col c) -> byte:  r*256 + ((c>>3) ^ (r&7))*16 + (c&7)*2
__device__ __forceinline__ void split2(float4 v, uint2& H, uint2& M) {
    float a[4] = {v.x, v.y, v.z, v.w};
    unsigned short hs[4], ms[4];
    #pragma unroll
    for (int i = 0; i < 4; i++) {
        __nv_bfloat16 hb = __float2bfloat16_rn(a[i]);
        float r1 = a[i] - __bfloat162float(hb);
        __nv_bfloat16 mb = __float2bfloat16_rn(r1);
        hs[i] = __bfloat16_as_ushort(hb);
        ms[i] = __bfloat16_as_ushort(mb);
    }
    H.x = hs[0] | ((uint32_t)hs[1] << 16); H.y = hs[2] | ((uint32_t)hs[3] << 16);
    M.x = ms[0] | ((uint32_t)ms[1] << 16); M.y = ms[2] | ((uint32_t)ms[3] << 16);
}

// ---------------------------------------------------------------------------
__global__ void prep_kernel(const float* __restrict__ cb) {
    int gr = blockIdx.x * blockDim.x + threadIdx.x;   // 0..8191
    if (gr >= QSTAGES * KCODES) return;
    int stage = gr >> 10, row = gr & 1023;
    int tile = row >> 6, r = row & 63;
    const float4* src = (const float4*)(cb + (size_t)gr * DDIM);
    unsigned char* base0 = g_cbs + (size_t)((stage * NTILES + tile) * 2) * B_TERM_BYTES;
    #pragma unroll 4
    for (int c4 = 0; c4 < 32; c4++) {
        uint2 H, M;
        split2(src[c4], H, M);
        uint32_t so = (uint32_t)r * 256 + (uint32_t)(((c4 >> 1) ^ (r & 7)) * 16)
                    + (uint32_t)((c4 & 1) * 8);
        *(uint2*)(base0 + so)                = H;
        *(uint2*)(base0 + B_TERM_BYTES + so) = M;
    }
}

// ---------------------------------------------------------------------------
__global__ void c2_kernel(const float* __restrict__ cb) {
    int warp = (blockIdx.x * blockDim.x + threadIdx.x) >> 5;
    int lane = threadIdx.x & 31;
    const float4* row = (const float4*)(cb + (size_t)warp * DDIM);
    float4 v = row[lane];
    float s = v.x * v.x + v.y * v.y + v.z * v.z + v.w * v.w;
    #pragma unroll
    for (int o = 16; o > 0; o >>= 1) s += __shfl_down_sync(0xffffffffu, s, o);
    if (lane == 0) g_c2[warp] = s;
}

// ---------------------------------------------------------------------------
extern __shared__ char sm[];

__global__ __launch_bounds__(NTHREADS, 1)
void stage_kernel(const float* __restrict__ x,
                  const float* __restrict__ cb_all,
                  float* __restrict__ out,
                  int stage, int is_last) {
    const uint32_t smb = smem_u32(sm);
    const int tid = threadIdx.x, wid = tid >> 5, lid = tid & 31;
    const int tok0 = blockIdx.x * BM;
    const int warpM = wid & 7, warpN = wid >> 3;   // 8 x 2 warp grid
    const float*  src = (stage == 0) ? x : (const float*)g_res;
    const float*  cbf = cb_all + (size_t)stage * KCODES * DDIM;
    const float4* cb4 = (const float4*)cbf;
    const float*  c2  = g_c2 + stage * KCODES;

    int*   chosen = (int*)(sm + CHOSEN_OFF);
    float* redv   = (float*)(sm + REDV_OFF);
    int*   redi   = (int*)(sm + REDI_OFF);
    float* redv2  = (float*)(sm + REDV2_OFF);
    int*   redi2  = (int*)(sm + REDI2_OFF);

    // ---- preload B tiles 0,1 ----
    const unsigned char* gcb = g_cbs + (size_t)(stage * NTILES * 2) * B_TERM_BYTES;
    {
        uint32_t b0 = smb + B_OFF, b1 = smb + B_OFF + B_BUF_BYTES;
        #pragma unroll
        for (int k = 0; k < 4; k++) {
            int u = tid + k * NTHREADS;   // 0..2047
            cp16(b0 + (uint32_t)u * 16, gcb + (size_t)u * 16);
        }
        cp_commit();
        #pragma unroll
        for (int k = 0; k < 4; k++) {
            int u = tid + k * NTHREADS;
            cp16(b1 + (uint32_t)u * 16, gcb + B_BUF_BYTES + (size_t)u * 16);
        }
        cp_commit();
    }

    // ---- A split: residual -> 2 bf16 planes in swizzled smem ----
    {
        const float4* s4 = (const float4*)src + (size_t)tok0 * 32;
        #pragma unroll
        for (int k = 0; k < 8; k++) {
            int f = tid + k * NTHREADS;
            int r = f >> 5, c4 = f & 31;
            uint2 H, M;
            split2(s4[f], H, M);
            uint32_t so = (uint32_t)r * 256 + (uint32_t)(((c4 >> 1) ^ (r & 7)) * 16)
                        + (uint32_t)((c4 & 1) * 8);
            *(uint2*)(sm + A_OFF + so)                = H;
            *(uint2*)(sm + A_OFF + A_TERM_BYTES + so) = M;
        }
    }
    __syncthreads();

    // ---- registerize A_H for this warp's 16 rows ----
    const int arow = warpM * 16 + (lid & 15);
    const uint32_t aRowByte = (uint32_t)arow * 256;
    const uint32_t aRx = (uint32_t)(arow & 7);
    const uint32_t aKh = (uint32_t)(lid >> 4);
    uint32_t aH[8][4];
    #pragma unroll
    for (int k8 = 0; k8 < 8; k8++) {
        uint32_t addr = smb + A_OFF + aRowByte
                      + ((((uint32_t)(2 * k8) + aKh) ^ aRx) << 4);
        ldsm4(aH[k8][0], aH[k8][1], aH[k8][2], aH[k8][3], addr);
    }
    const uint32_t aMplane = smb + A_OFF + A_TERM_BYTES;

    // B lane addressing
    uint32_t bRowByte[2], bRx[2];
    #pragma unroll
    for (int pi = 0; pi < 2; pi++) {
        int row = warpN * 32 + pi * 16 + ((lid >> 4) << 3) + (lid & 7);
        bRowByte[pi] = (uint32_t)row * 256;
        bRx[pi] = (uint32_t)(row & 7);
    }
    const uint32_t bKh = (uint32_t)((lid >> 3) & 1);

    // per-thread top-2 per h (this warp's rows: warpM*16 + h*8 + lid/4)
    float b1v[2], b2v[2]; int b1i[2], b2i[2];
    #pragma unroll
    for (int h = 0; h < 2; h++) {
        b1v[h] = 3.4e38f; b2v[h] = 3.4e38f; b1i[h] = 0; b2i[h] = 0;
    }

    for (int t = 0; t < NTILES; t++) {
        if (t < NTILES - 1) cp_wait<1>(); else cp_wait<0>();
        __syncthreads();
        const uint32_t bbuf = smb + B_OFF + (uint32_t)(t & 1) * B_BUF_BYTES;

        float acc[4][4];
        #pragma unroll
        for (int ni = 0; ni < 4; ni++)
            #pragma unroll
            for (int q = 0; q < 4; q++) acc[ni][q] = 0.f;

        #pragma unroll
        for (int k8 = 0; k8 < 8; k8++) {
            const uint32_t ku = (uint32_t)(2 * k8);
            // B_H, B_M fragments (2 LDSM each), A_M fragment (1 LDSM)
            uint32_t bH[2][4], bMt[2][4], aM[4];
            #pragma unroll
            for (int pi = 0; pi < 2; pi++) {
                uint32_t koff = (((ku + bKh) ^ bRx[pi]) << 4);
                ldsm4(bH[pi][0], bH[pi][1], bH[pi][2], bH[pi][3],
                      bbuf + bRowByte[pi] + koff);
                ldsm4(bMt[pi][0], bMt[pi][1], bMt[pi][2], bMt[pi][3],
                      bbuf + B_TERM_BYTES + bRowByte[pi] + koff);
            }
            {
                uint32_t addr = aMplane + aRowByte + (((ku + aKh) ^ aRx) << 4);
                ldsm4(aM[0], aM[1], aM[2], aM[3], addr);
            }
            #pragma unroll
            for (int pi = 0; pi < 2; pi++) {
                // HH
                mma16816(acc[pi*2][0], acc[pi*2][1], acc[pi*2][2], acc[pi*2][3],
                         aH[k8][0], aH[k8][1], aH[k8][2], aH[k8][3],
                         bH[pi][0], bH[pi][1]);
                mma16816(acc[pi*2+1][0], acc[pi*2+1][1], acc[pi*2+1][2], acc[pi*2+1][3],
                         aH[k8][0], aH[k8][1], aH[k8][2], aH[k8][3],
                         bH[pi][2], bH[pi][3]);
                // HM
                mma16816(acc[pi*2][0], acc[pi*2][1], acc[pi*2][2], acc[pi*2][3],
                         aH[k8][0], aH[k8][1], aH[k8][2], aH[k8][3],
                         bMt[pi][0], bMt[pi][1]);
                mma16816(acc[pi*2+1][0], acc[pi*2+1][1], acc[pi*2+1][2], acc[pi*2+1][3],
                         aH[k8][0], aH[k8][1], aH[k8][2], aH[k8][3],
                         bMt[pi][2], bMt[pi][3]);
                // MH
                mma16816(acc[pi*2][0], acc[pi*2][1], acc[pi*2][2], acc[pi*2][3],
                         aM[0], aM[1], aM[2], aM[3],
                         bH[pi][0], bH[pi][1]);
                mma16816(acc[pi*2+1][0], acc[pi*2+1][1], acc[pi*2+1][2], acc[pi*2+1][3],
                         aM[0], aM[1], aM[2], aM[3],
                         bH[pi][2], bH[pi][3]);
            }
        }

        // top-2 argmin epilogue (ascending code order)
        const int codebase = t * NTILE + warpN * 32;
        #pragma unroll
        for (int ni = 0; ni < 4; ni++) {
            int code0 = codebase + ni * 8 + (lid & 3) * 2;
            float2 cc = __ldg((const float2*)(c2 + code0));
            #pragma unroll
            for (int h = 0; h < 2; h++) {
                float d0 = cc.x - 2.f * acc[ni][h * 2];
                float d1 = cc.y - 2.f * acc[ni][h * 2 + 1];
                if (d0 < b1v[h]) {
                    b2v[h] = b1v[h]; b2i[h] = b1i[h];
                    b1v[h] = d0; b1i[h] = code0;
                } else if (d0 < b2v[h]) { b2v[h] = d0; b2i[h] = code0; }
                if (d1 < b1v[h]) {
                    b2v[h] = b1v[h]; b2i[h] = b1i[h];
                    b1v[h] = d1; b1i[h] = code0 + 1;
                } else if (d1 < b2v[h]) { b2v[h] = d1; b2i[h] = code0 + 1; }
            }
        }

        __syncthreads();
        if (t + 2 < NTILES) {
            uint32_t bb = smb + B_OFF + (uint32_t)(t & 1) * B_BUF_BYTES;
            const unsigned char* gs = gcb + (size_t)(t + 2) * B_BUF_BYTES;
            #pragma unroll
            for (int k = 0; k < 4; k++) {
                int u = tid + k * NTHREADS;
                cp16(bb + (uint32_t)u * 16, gs + (size_t)u * 16);
            }
            cp_commit();
        }
    }

    // quad reduce (lanes with same rows differ in bits 0-1), write per-warpN
    #pragma unroll
    for (int h = 0; h < 2; h++) {
        float v1 = b1v[h], v2 = b2v[h];
        int   j1 = b1i[h], j2 = b2i[h];
        #pragma unroll
        for (int off = 1; off <= 2; off <<= 1) {
            float o1 = __shfl_xor_sync(0xffffffffu, v1, off);
            int   oj1 = __shfl_xor_sync(0xffffffffu, j1, off);
            float o2 = __shfl_xor_sync(0xffffffffu, v2, off);
            int   oj2 = __shfl_xor_sync(0xffffffffu, j2, off);
            merge2(v1, j1, v2, j2, o1, oj1, o2, oj2);
        }
        if ((lid & 3) == 0) {
            int row = warpM * 16 + h * 8 + (lid >> 2);
            redv[warpN * 128 + row]  = v1;
            redi[warpN * 128 + row]  = j1;
            redv2[warpN * 128 + row] = v2;
            redi2[warpN * 128 + row] = j2;
        }
    }
    __syncthreads();

    // exact fp32 rescue: thread (token, contributor) recomputes both candidates
    if (tid < 256) {
        int token = tid >> 1, c = tid & 1;
        int j1 = redi[c * 128 + token];
        int j2 = redi2[c * 128 + token];
        const float* rrow = src + (size_t)(tok0 + token) * DDIM;
        const float* c1row = cbf + (size_t)j1 * DDIM;
        const float* c2row = cbf + (size_t)j2 * DDIM;
        float acc1 = 0.f, acc2 = 0.f;
        #pragma unroll 16
        for (int d = 0; d < DDIM; d++) {
            float r = __ldg(&rrow[d]);
            acc1 = fmaf(r, __ldg(&c1row[d]), acc1);
            acc2 = fmaf(r, __ldg(&c2row[d]), acc2);
        }
        redv[c * 128 + token]  = __ldg(&c2[j1]) - 2.f * acc1;
        redv2[c * 128 + token] = __ldg(&c2[j2]) - 2.f * acc2;
    }
    __syncthreads();
    if (tid < BM) {
        float bv = 3.4e38f; int bi = 0x7fffffff;
        #pragma unroll
        for (int c = 0; c < 2; c++) {
            float v1 = redv[c * 128 + tid];  int j1 = redi[c * 128 + tid];
            float v2 = redv2[c * 128 + tid]; int j2 = redi2[c * 128 + tid];
            if (dless(v1, j1, bv, bi)) { bv = v1; bi = j1; }
            if (dless(v2, j2, bv, bi)) { bv = v2; bi = j2; }
        }
        chosen[tid] = bi;
        out[(size_t)(tok0 + tid) * QSTAGES + stage] = (float)bi;
    }
    __syncthreads();

    // residual update + commit partial + optional quantized output (fp32 exact)
    float4*       res4 = (float4*)g_res + (size_t)tok0 * 32;
    const float4* s4   = (const float4*)src + (size_t)tok0 * 32;
    const float4* x4   = (const float4*)x + (size_t)tok0 * 32;
    float4*       q4   = (float4*)(out + (size_t)TOKENS * QSTAGES) + (size_t)tok0 * 32;

    float psum = 0.f;
    #pragma unroll
    for (int k = 0; k < 8; k++) {
        int f = tid + k * NTHREADS;
        int tk = f >> 5, d4 = f & 31;
        float4 rv = s4[f];
        float4 cv = cb4[(size_t)chosen[tk] * 32 + d4];
        float4 nv = make_float4(rv.x - cv.x, rv.y - cv.y, rv.z - cv.z, rv.w - cv.w);
        res4[tk * 32 + d4] = nv;
        psum += nv.x * nv.x + nv.y * nv.y + nv.z * nv.z + nv.w * nv.w;
        if (is_last) {
            float4 xv = x4[f];
            q4[tk * 32 + d4] = make_float4(xv.x - nv.x, xv.y - nv.y,
                                           xv.z - nv.z, xv.w - nv.w);
        }
    }
    #pragma unroll
    for (int o = 16; o > 0; o >>= 1) psum += __shfl_down_sync(0xffffffffu, psum, o);
    __syncthreads();
    if (lid == 0) redv[wid] = psum;
    __syncthreads();
    if (tid == 0) {
        float s = 0.f;
        #pragma unroll
        for (int w2 = 0; w2 < 16; w2++) s += redv[w2];
        g_partial[stage * NBLOCKS + blockIdx.x] = s;
    }
}

// ---------------------------------------------------------------------------
__global__ void finish_kernel(float* __restrict__ out) {
    int q = threadIdx.x;
    if (q < QSTAGES) {
        float s = 0.f;
        for (int b = 0; b < NBLOCKS; b++) s += g_partial[q * NBLOCKS + b];
        out[(size_t)TOKENS * QSTAGES + (size_t)TOKENS * DDIM + q] =
            s / (float)(TOKENS * DDIM);
    }
}

extern "C" void kernel_launch(void* const* d_in, const int* in_sizes, int n_in,
                              void* d_out, int out_size) {
    const float* x  = (const float*)d_in[0];
    const float* cb = (const float*)d_in[1];
    float* out = (float*)d_out;

    cudaFuncSetAttribute(stage_kernel,
                         cudaFuncAttributeMaxDynamicSharedMemorySize, SMEM_TOTAL);

    prep_kernel<<<64, 128>>>(cb);
    c2_kernel<<<1024, 256>>>(cb);
    for (int s = 0; s < QSTAGES; s++) {
        stage_kernel<<<NBLOCKS, NTHREADS, SMEM_TOTAL>>>(x, cb, out, s,
                                                        (s == QSTAGES - 1) ? 1 : 0);
    }
    finish_kernel<<<1, 32>>>(out);
}